// round 1
// baseline (speedup 1.0000x reference)
#include <cuda_runtime.h>
#include <cuda_bf16.h>
#include <cstddef>

// Problem constants
#define B_  2
#define S_  2048
#define D_  1024
#define H_  16
#define HD_ 64
#define M_  (B_ * S_)          // 4096 rows for projection GEMMs

// Scratch (device globals; no allocation allowed)
__device__ float g_Q[(size_t)B_ * H_ * S_ * HD_];   // [bh][s][e]
__device__ float g_K[(size_t)B_ * H_ * S_ * HD_];
__device__ float g_V[(size_t)B_ * H_ * S_ * HD_];
__device__ float g_ctx[(size_t)B_ * S_ * D_];        // [b][s][h*64+e]

// ---------------------------------------------------------------------------
// Fast exp: FMA-pipe polynomial (avoids MUFU throughput wall: 134M exps)
// exp(x) for x <= ~0. Accurate to ~4e-5 relative.
// ---------------------------------------------------------------------------
__device__ __forceinline__ float fast_exp(float x) {
    float t = fmaxf(x * 1.4426950408889634f, -60.0f); // log2(e), clamp
    float n = rintf(t);
    float f = t - n;                 // f in [-0.5, 0.5]
    float u = f * 0.6931471805599453f; // ln2
    float p = fmaf(u, 0.0416666679f, 0.1666666667f);
    p = fmaf(p, u, 0.5f);
    p = fmaf(p, u, 1.0f);
    p = fmaf(p, u, 1.0f);
    int e = (((int)n) + 127) << 23;
    return __int_as_float(e) * p;
}

// ---------------------------------------------------------------------------
// SGEMM: out[M=4096, N=1024] = X[4096,1024] @ W + bias
// headstack=1: W is [H, D, HD] (per-head stacked), output written as
//              [bh][s][e]  (for Q/K/V scratch).
// headstack=0: W is [D, D] row-major, output written as [m][n] (row-major).
// BM=BN=64, BK=16, 256 threads, 4x4 per-thread tile.
// ---------------------------------------------------------------------------
__global__ void gemm_kernel(const float* __restrict__ X,
                            const float* __restrict__ W,
                            const float* __restrict__ bias,
                            float* __restrict__ out,
                            int headstack) {
    __shared__ float As[16][65];   // A transposed [k][m], pad -> conflict-free
    __shared__ float Bs[16][64];   // B natural    [k][n]

    const int tid = threadIdx.x;
    const int tx = tid & 15;       // 0..15 -> n micro
    const int ty = tid >> 4;       // 0..15 -> m micro
    const int bx = blockIdx.x;     // n tile (and head id when headstack)
    const int by = blockIdx.y;     // m tile
    const int m0 = by * 64;
    const int n0 = bx * 64;

    const float* Wb = headstack ? (W + (size_t)bx * (D_ * HD_)) : (W + n0);
    const int ldw = headstack ? HD_ : D_;

    // load mappings
    const int lm = tid >> 2;          // 0..63  A row
    const int lk = (tid & 3) * 4;     // 0,4,8,12  A k (float4)
    const int bk = tid >> 4;          // 0..15  B row
    const int bn = (tid & 15) * 4;    // B col (float4)

    float acc[4][4] = {};

    for (int k0 = 0; k0 < D_; k0 += 16) {
        float4 av = *reinterpret_cast<const float4*>(
            &X[(size_t)(m0 + lm) * D_ + k0 + lk]);
        float4 bv = *reinterpret_cast<const float4*>(
            &Wb[(size_t)(k0 + bk) * ldw + bn]);
        As[lk + 0][lm] = av.x;
        As[lk + 1][lm] = av.y;
        As[lk + 2][lm] = av.z;
        As[lk + 3][lm] = av.w;
        *reinterpret_cast<float4*>(&Bs[bk][bn]) = bv;
        __syncthreads();

#pragma unroll
        for (int kk = 0; kk < 16; ++kk) {
            float a0 = As[kk][4 * ty + 0];
            float a1 = As[kk][4 * ty + 1];
            float a2 = As[kk][4 * ty + 2];
            float a3 = As[kk][4 * ty + 3];
            float4 b = *reinterpret_cast<const float4*>(&Bs[kk][4 * tx]);
            acc[0][0] = fmaf(a0, b.x, acc[0][0]);
            acc[0][1] = fmaf(a0, b.y, acc[0][1]);
            acc[0][2] = fmaf(a0, b.z, acc[0][2]);
            acc[0][3] = fmaf(a0, b.w, acc[0][3]);
            acc[1][0] = fmaf(a1, b.x, acc[1][0]);
            acc[1][1] = fmaf(a1, b.y, acc[1][1]);
            acc[1][2] = fmaf(a1, b.z, acc[1][2]);
            acc[1][3] = fmaf(a1, b.w, acc[1][3]);
            acc[2][0] = fmaf(a2, b.x, acc[2][0]);
            acc[2][1] = fmaf(a2, b.y, acc[2][1]);
            acc[2][2] = fmaf(a2, b.z, acc[2][2]);
            acc[2][3] = fmaf(a2, b.w, acc[2][3]);
            acc[3][0] = fmaf(a3, b.x, acc[3][0]);
            acc[3][1] = fmaf(a3, b.y, acc[3][1]);
            acc[3][2] = fmaf(a3, b.z, acc[3][2]);
            acc[3][3] = fmaf(a3, b.w, acc[3][3]);
        }
        __syncthreads();
    }

    // epilogue + bias
    float b0 = bias[n0 + 4 * tx + 0];
    float b1 = bias[n0 + 4 * tx + 1];
    float b2 = bias[n0 + 4 * tx + 2];
    float b3 = bias[n0 + 4 * tx + 3];

    if (!headstack) {
#pragma unroll
        for (int i = 0; i < 4; ++i) {
            int r = m0 + 4 * ty + i;
            float4 v;
            v.x = acc[i][0] + b0;
            v.y = acc[i][1] + b1;
            v.z = acc[i][2] + b2;
            v.w = acc[i][3] + b3;
            *reinterpret_cast<float4*>(&out[(size_t)r * D_ + n0 + 4 * tx]) = v;
        }
    } else {
#pragma unroll
        for (int i = 0; i < 4; ++i) {
            int r = m0 + 4 * ty + i;
            int bb = r >> 11;          // / S_
            int ss = r & (S_ - 1);
            size_t base = ((size_t)(bb * H_ + bx) * S_ + ss) * HD_ + 4 * tx;
            float4 v;
            v.x = acc[i][0] + b0;
            v.y = acc[i][1] + b1;
            v.z = acc[i][2] + b2;
            v.w = acc[i][3] + b3;
            *reinterpret_cast<float4*>(&out[base]) = v;
        }
    }
}

// ---------------------------------------------------------------------------
// Flash attention, fp32. One block = 64 query rows of one (b,h).
// Grid: (S/64 = 32, B*H = 32). 256 threads (16x16), 4x4 micro-tiles.
// Shared: Qs[64][68] (natural), KVs[64][65] (K then V), Ps[64][65] (P^T).
// All inner-loop shared reads are bank-conflict-free by stride choice.
// ---------------------------------------------------------------------------
#define QS_STR 68
#define KV_STR 65
#define PS_STR 65
#define ATT_SMEM ((64 * QS_STR + 64 * KV_STR + 64 * PS_STR) * 4)

__global__ void attn_kernel(const float* __restrict__ Q,
                            const float* __restrict__ K,
                            const float* __restrict__ V,
                            float* __restrict__ ctx) {
    extern __shared__ float sm[];
    float* Qs = sm;                       // [64][QS_STR]
    float* KVs = sm + 64 * QS_STR;        // [64][KV_STR]
    float* Ps = sm + 64 * QS_STR + 64 * KV_STR; // [64][PS_STR] (P transposed)

    const int tid = threadIdx.x;
    const int tx = tid & 15;
    const int ty = tid >> 4;
    const int qt = blockIdx.x;
    const int bh = blockIdx.y;

    // Load Q tile [64 x 64] (natural layout, float4 stores, stride 68 aligned)
    {
        const size_t qbase = ((size_t)bh * S_ + qt * 64) * HD_;
#pragma unroll
        for (int l = 0; l < 4; ++l) {
            int f4 = tid + 256 * l;          // 0..1023
            int si = f4 >> 4;
            int e4 = (f4 & 15) * 4;
            float4 v = *reinterpret_cast<const float4*>(&Q[qbase + (size_t)si * HD_ + e4]);
            *reinterpret_cast<float4*>(&Qs[si * QS_STR + e4]) = v;
        }
    }

    float m_i[4], l_i[4], o[4][4];
#pragma unroll
    for (int i = 0; i < 4; ++i) {
        m_i[i] = -1e30f;
        l_i[i] = 0.0f;
#pragma unroll
        for (int j = 0; j < 4; ++j) o[i][j] = 0.0f;
    }
    __syncthreads();

    const size_t kvhead = (size_t)bh * S_ * HD_;

    for (int kt = 0; kt < S_ / 64; ++kt) {
        const size_t kb = kvhead + (size_t)kt * 64 * HD_;

        // ---- load K tile into KVs (scalar stores -> conflict-free reads) ----
#pragma unroll
        for (int l = 0; l < 4; ++l) {
            int f4 = tid + 256 * l;
            int ci = f4 >> 4;
            int e4 = (f4 & 15) * 4;
            float4 v = *reinterpret_cast<const float4*>(&K[kb + (size_t)ci * HD_ + e4]);
            KVs[ci * KV_STR + e4 + 0] = v.x;
            KVs[ci * KV_STR + e4 + 1] = v.y;
            KVs[ci * KV_STR + e4 + 2] = v.z;
            KVs[ci * KV_STR + e4 + 3] = v.w;
        }
        __syncthreads();

        // ---- scores: S = Q @ K^T   (thread cols = tx, tx+16, tx+32, tx+48) --
        float s_[4][4] = {};
#pragma unroll 8
        for (int e = 0; e < HD_; ++e) {
            float a0 = Qs[(4 * ty + 0) * QS_STR + e];
            float a1 = Qs[(4 * ty + 1) * QS_STR + e];
            float a2 = Qs[(4 * ty + 2) * QS_STR + e];
            float a3 = Qs[(4 * ty + 3) * QS_STR + e];
            float c0 = KVs[(tx + 0) * KV_STR + e];
            float c1 = KVs[(tx + 16) * KV_STR + e];
            float c2 = KVs[(tx + 32) * KV_STR + e];
            float c3 = KVs[(tx + 48) * KV_STR + e];
            s_[0][0] = fmaf(a0, c0, s_[0][0]);
            s_[0][1] = fmaf(a0, c1, s_[0][1]);
            s_[0][2] = fmaf(a0, c2, s_[0][2]);
            s_[0][3] = fmaf(a0, c3, s_[0][3]);
            s_[1][0] = fmaf(a1, c0, s_[1][0]);
            s_[1][1] = fmaf(a1, c1, s_[1][1]);
            s_[1][2] = fmaf(a1, c2, s_[1][2]);
            s_[1][3] = fmaf(a1, c3, s_[1][3]);
            s_[2][0] = fmaf(a2, c0, s_[2][0]);
            s_[2][1] = fmaf(a2, c1, s_[2][1]);
            s_[2][2] = fmaf(a2, c2, s_[2][2]);
            s_[2][3] = fmaf(a2, c3, s_[2][3]);
            s_[3][0] = fmaf(a3, c0, s_[3][0]);
            s_[3][1] = fmaf(a3, c1, s_[3][1]);
            s_[3][2] = fmaf(a3, c2, s_[3][2]);
            s_[3][3] = fmaf(a3, c3, s_[3][3]);
        }
        __syncthreads();

        // ---- load V tile into KVs (same layout) -----------------------------
        const size_t vb = kb;
#pragma unroll
        for (int l = 0; l < 4; ++l) {
            int f4 = tid + 256 * l;
            int ci = f4 >> 4;
            int e4 = (f4 & 15) * 4;
            float4 v = *reinterpret_cast<const float4*>(&V[vb + (size_t)ci * HD_ + e4]);
            KVs[ci * KV_STR + e4 + 0] = v.x;
            KVs[ci * KV_STR + e4 + 1] = v.y;
            KVs[ci * KV_STR + e4 + 2] = v.z;
            KVs[ci * KV_STR + e4 + 3] = v.w;
        }

        // ---- online softmax on this tile ------------------------------------
#pragma unroll
        for (int i = 0; i < 4; ++i) {
            float sc0 = s_[i][0] * 0.125f;
            float sc1 = s_[i][1] * 0.125f;
            float sc2 = s_[i][2] * 0.125f;
            float sc3 = s_[i][3] * 0.125f;
            float mx = fmaxf(fmaxf(sc0, sc1), fmaxf(sc2, sc3));
#pragma unroll
            for (int off = 1; off < 16; off <<= 1)
                mx = fmaxf(mx, __shfl_xor_sync(0xffffffffu, mx, off, 16));
            float mn = fmaxf(m_i[i], mx);
            float corr = fast_exp(m_i[i] - mn);
            float p0 = fast_exp(sc0 - mn);
            float p1 = fast_exp(sc1 - mn);
            float p2 = fast_exp(sc2 - mn);
            float p3 = fast_exp(sc3 - mn);
            float rs = p0 + p1 + p2 + p3;
#pragma unroll
            for (int off = 1; off < 16; off <<= 1)
                rs += __shfl_xor_sync(0xffffffffu, rs, off, 16);
            l_i[i] = l_i[i] * corr + rs;
            o[i][0] *= corr;
            o[i][1] *= corr;
            o[i][2] *= corr;
            o[i][3] *= corr;
            m_i[i] = mn;
            // write P transposed: Ps[c][r]
            Ps[(tx + 0) * PS_STR + 4 * ty + i] = p0;
            Ps[(tx + 16) * PS_STR + 4 * ty + i] = p1;
            Ps[(tx + 32) * PS_STR + 4 * ty + i] = p2;
            Ps[(tx + 48) * PS_STR + 4 * ty + i] = p3;
        }
        __syncthreads();

        // ---- O += P @ V -----------------------------------------------------
#pragma unroll 8
        for (int c = 0; c < 64; ++c) {
            float a0 = Ps[c * PS_STR + 4 * ty + 0];
            float a1 = Ps[c * PS_STR + 4 * ty + 1];
            float a2 = Ps[c * PS_STR + 4 * ty + 2];
            float a3 = Ps[c * PS_STR + 4 * ty + 3];
            float v0 = KVs[c * KV_STR + tx + 0];
            float v1 = KVs[c * KV_STR + tx + 16];
            float v2 = KVs[c * KV_STR + tx + 32];
            float v3 = KVs[c * KV_STR + tx + 48];
            o[0][0] = fmaf(a0, v0, o[0][0]);
            o[0][1] = fmaf(a0, v1, o[0][1]);
            o[0][2] = fmaf(a0, v2, o[0][2]);
            o[0][3] = fmaf(a0, v3, o[0][3]);
            o[1][0] = fmaf(a1, v0, o[1][0]);
            o[1][1] = fmaf(a1, v1, o[1][1]);
            o[1][2] = fmaf(a1, v2, o[1][2]);
            o[1][3] = fmaf(a1, v3, o[1][3]);
            o[2][0] = fmaf(a2, v0, o[2][0]);
            o[2][1] = fmaf(a2, v1, o[2][1]);
            o[2][2] = fmaf(a2, v2, o[2][2]);
            o[2][3] = fmaf(a2, v3, o[2][3]);
            o[3][0] = fmaf(a3, v0, o[3][0]);
            o[3][1] = fmaf(a3, v1, o[3][1]);
            o[3][2] = fmaf(a3, v2, o[3][2]);
            o[3][3] = fmaf(a3, v3, o[3][3]);
        }
        __syncthreads();   // protect KVs/Ps before next tile overwrites
    }

    // ---- epilogue: normalize, write ctx[b][s][h*64+e] ----
    const int bb = bh >> 4;
    const int hh = bh & 15;
#pragma unroll
    for (int i = 0; i < 4; ++i) {
        float inv = 1.0f / l_i[i];
        int ss = qt * 64 + 4 * ty + i;
        size_t base = ((size_t)bb * S_ + ss) * D_ + hh * HD_;
#pragma unroll
        for (int j = 0; j < 4; ++j) {
            ctx[base + tx + 16 * j] = o[i][j] * inv;
        }
    }
}

// ---------------------------------------------------------------------------
// Launch
// ---------------------------------------------------------------------------
extern "C" void kernel_launch(void* const* d_in, const int* in_sizes, int n_in,
                              void* d_out, int out_size) {
    const float* x  = (const float*)d_in[0];
    const float* Wq = (const float*)d_in[1];
    const float* bq = (const float*)d_in[2];
    const float* Wk = (const float*)d_in[3];
    const float* bk = (const float*)d_in[4];
    const float* Wv = (const float*)d_in[5];
    const float* bv = (const float*)d_in[6];
    const float* Wo = (const float*)d_in[7];
    const float* bo = (const float*)d_in[8];
    float* out = (float*)d_out;

    float *Qp, *Kp, *Vp, *Cp;
    cudaGetSymbolAddress((void**)&Qp, g_Q);
    cudaGetSymbolAddress((void**)&Kp, g_K);
    cudaGetSymbolAddress((void**)&Vp, g_V);
    cudaGetSymbolAddress((void**)&Cp, g_ctx);

    cudaFuncSetAttribute(attn_kernel,
                         cudaFuncAttributeMaxDynamicSharedMemorySize, ATT_SMEM);

    dim3 gproj(D_ / 64, M_ / 64);   // (16, 64)
    gemm_kernel<<<gproj, 256>>>(x, Wq, bq, Qp, 1);
    gemm_kernel<<<gproj, 256>>>(x, Wk, bk, Kp, 1);
    gemm_kernel<<<gproj, 256>>>(x, Wv, bv, Vp, 1);

    attn_kernel<<<dim3(S_ / 64, B_ * H_), 256, ATT_SMEM>>>(Qp, Kp, Vp, Cp);

    gemm_kernel<<<gproj, 256>>>(Cp, Wo, bo, out, 0);
}

// round 2
// speedup vs baseline: 1.0597x; 1.0597x over previous
#include <cuda_runtime.h>
#include <cuda_bf16.h>
#include <cstddef>

// Problem constants
#define B_  2
#define S_  2048
#define D_  1024
#define H_  16
#define HD_ 64
#define M_  (B_ * S_)

typedef unsigned long long u64;

// Scratch (device globals; no allocation allowed)
__device__ float g_Q[(size_t)B_ * H_ * S_ * HD_];   // [bh][s][e]
__device__ float g_K[(size_t)B_ * H_ * S_ * HD_];
__device__ float g_V[(size_t)B_ * H_ * S_ * HD_];
__device__ float g_ctx[(size_t)B_ * S_ * D_];       // [b][s][h*64+e]

// ---------------------------------------------------------------------------
// Packed f32x2 helpers (FFMA2 path — ptxas never emits these from C++)
// ---------------------------------------------------------------------------
__device__ __forceinline__ u64 ffma2(u64 a, u64 b, u64 c) {
    u64 d;
    asm("fma.rn.f32x2 %0, %1, %2, %3;" : "=l"(d) : "l"(a), "l"(b), "l"(c));
    return d;
}
__device__ __forceinline__ u64 fmul2(u64 a, u64 b) {
    u64 d;
    asm("mul.rn.f32x2 %0, %1, %2;" : "=l"(d) : "l"(a), "l"(b));
    return d;
}
__device__ __forceinline__ u64 dup2(float x) {
    u64 d;
    asm("mov.b64 %0, {%1, %1};" : "=l"(d) : "f"(x));
    return d;
}
__device__ __forceinline__ float lo32(u64 v) { return __uint_as_float((unsigned)v); }
__device__ __forceinline__ float hi32(u64 v) { return __uint_as_float((unsigned)(v >> 32)); }
__device__ __forceinline__ float fold2(u64 v) { return lo32(v) + hi32(v); }

// ---------------------------------------------------------------------------
// Fast exp on the FMA pipe (MUFU throughput wall avoidance)
// ---------------------------------------------------------------------------
__device__ __forceinline__ float fast_exp(float x) {
    float t = fmaxf(x * 1.4426950408889634f, -60.0f);
    float n = rintf(t);
    float f = t - n;
    float u = f * 0.6931471805599453f;
    float p = fmaf(u, 0.0416666679f, 0.1666666667f);
    p = fmaf(p, u, 0.5f);
    p = fmaf(p, u, 1.0f);
    p = fmaf(p, u, 1.0f);
    int e = (((int)n) + 127) << 23;
    return __int_as_float(e) * p;
}

// ---------------------------------------------------------------------------
// SGEMM with FFMA2 (K-paired accumulators).
// out[4096, 1024] = X @ W + bias.  BM=BN=64, BK=32, 256 threads, 4x4 micro.
// As[m][k] natural (X rows are k-contiguous).  Bs[n][k] transposed via
// coalesced scalar gmem loads + STS.128.
// ---------------------------------------------------------------------------
#define GK 32
#define GSTR 36   // 36 floats: 144B row (16B-aligned, 9 quads = odd -> conflict floor)

__global__ __launch_bounds__(256) void gemm_kernel(const float* __restrict__ X,
                                                   const float* __restrict__ W,
                                                   const float* __restrict__ bias,
                                                   float* __restrict__ out,
                                                   int headstack) {
    __shared__ float As[64][GSTR];
    __shared__ float Bs[64][GSTR];

    const int tid = threadIdx.x;
    const int tx = tid & 15;
    const int ty = tid >> 4;
    const int bx = blockIdx.x;     // n tile / head
    const int by = blockIdx.y;
    const int m0 = by * 64;
    const int n0 = bx * 64;

    const float* Wb = headstack ? (W + (size_t)bx * (D_ * HD_)) : (W + n0);
    const int ldw = headstack ? HD_ : D_;

    // load maps
    const int lm = tid >> 2;               // A row 0..63
    const int lk = (tid & 3) * 8;          // A k base (two float4)
    const int nn = tid & 63;               // B col 0..63
    const int kq = (tid >> 6) * 8;         // B k base (8 scalars)

    u64 acc2[4][4];
#pragma unroll
    for (int i = 0; i < 4; ++i)
#pragma unroll
        for (int j = 0; j < 4; ++j) acc2[i][j] = 0ull;

    for (int k0 = 0; k0 < D_; k0 += GK) {
        float4 av0 = *reinterpret_cast<const float4*>(&X[(size_t)(m0 + lm) * D_ + k0 + lk]);
        float4 av1 = *reinterpret_cast<const float4*>(&X[(size_t)(m0 + lm) * D_ + k0 + lk + 4]);
        float wv[8];
#pragma unroll
        for (int i = 0; i < 8; ++i)
            wv[i] = Wb[(size_t)(k0 + kq + i) * ldw + nn];

        *reinterpret_cast<float4*>(&As[lm][lk]) = av0;
        *reinterpret_cast<float4*>(&As[lm][lk + 4]) = av1;
        float4 b0 = make_float4(wv[0], wv[1], wv[2], wv[3]);
        float4 b1 = make_float4(wv[4], wv[5], wv[6], wv[7]);
        *reinterpret_cast<float4*>(&Bs[nn][kq]) = b0;
        *reinterpret_cast<float4*>(&Bs[nn][kq + 4]) = b1;
        __syncthreads();

#pragma unroll
        for (int k4 = 0; k4 < GK; k4 += 4) {
            ulonglong2 a[4], b[4];
#pragma unroll
            for (int i = 0; i < 4; ++i)
                a[i] = *reinterpret_cast<const ulonglong2*>(&As[4 * ty + i][k4]);
#pragma unroll
            for (int j = 0; j < 4; ++j)
                b[j] = *reinterpret_cast<const ulonglong2*>(&Bs[tx + 16 * j][k4]);
#pragma unroll
            for (int i = 0; i < 4; ++i)
#pragma unroll
                for (int j = 0; j < 4; ++j) {
                    acc2[i][j] = ffma2(a[i].x, b[j].x, acc2[i][j]);
                    acc2[i][j] = ffma2(a[i].y, b[j].y, acc2[i][j]);
                }
        }
        __syncthreads();
    }

    // fold + bias + store
    float bb_[4];
#pragma unroll
    for (int j = 0; j < 4; ++j) bb_[j] = bias[n0 + tx + 16 * j];

    if (!headstack) {
#pragma unroll
        for (int i = 0; i < 4; ++i) {
            int r = m0 + 4 * ty + i;
#pragma unroll
            for (int j = 0; j < 4; ++j)
                out[(size_t)r * D_ + n0 + tx + 16 * j] = fold2(acc2[i][j]) + bb_[j];
        }
    } else {
#pragma unroll
        for (int i = 0; i < 4; ++i) {
            int r = m0 + 4 * ty + i;
            int bb = r >> 11;
            int ss = r & (S_ - 1);
            size_t base = ((size_t)(bb * H_ + bx) * S_ + ss) * HD_;
#pragma unroll
            for (int j = 0; j < 4; ++j)
                out[base + tx + 16 * j] = fold2(acc2[i][j]) + bb_[j];
        }
    }
}

// ---------------------------------------------------------------------------
// Flash attention with FFMA2.
// Block = 64 q-rows of one (b,h). 256 threads (16x16). 4x4 micro tiles.
// Scores: K-pair along e (both operands natural LDS.128, no packs).
// PV:     K-pair along c; P stored pre-duplicated (Psd[q][2c]=(p,p)) so the
//         broadcast operand needs no packs either. V stays natural [c][e].
// ---------------------------------------------------------------------------
#define TSTR 68     // 68 floats: 272B rows (aligned, 17 quads odd)
#define PSTR 132    // dup'd P row: 132 floats (528B aligned, 33 quads odd)
#define ATT_FLOATS (64 * TSTR * 3 + 64 * PSTR)
#define ATT_SMEM (ATT_FLOATS * 4)

__global__ __launch_bounds__(256) void attn_kernel(const float* __restrict__ Q,
                                                   const float* __restrict__ K,
                                                   const float* __restrict__ V,
                                                   float* __restrict__ ctx) {
    extern __shared__ float sm[];
    float* Qs = sm;                        // [64][TSTR]
    float* Ks = sm + 64 * TSTR;            // [64][TSTR]
    float* Vs = sm + 2 * 64 * TSTR;        // [64][TSTR]
    float* Psd = sm + 3 * 64 * TSTR;       // [64][PSTR]

    const int tid = threadIdx.x;
    const int tx = tid & 15;
    const int ty = tid >> 4;
    const int qt = blockIdx.x;
    const int bh = blockIdx.y;

    // Load Q tile (natural [q][e], float4)
    {
        const size_t qbase = ((size_t)bh * S_ + qt * 64) * HD_;
#pragma unroll
        for (int l = 0; l < 4; ++l) {
            int f4 = tid + 256 * l;
            int si = f4 >> 4;
            int e4 = (f4 & 15) * 4;
            *reinterpret_cast<float4*>(&Qs[si * TSTR + e4]) =
                *reinterpret_cast<const float4*>(&Q[qbase + (size_t)si * HD_ + e4]);
        }
    }

    float m_i[4], l_i[4];
    u64 o2[4][2];
#pragma unroll
    for (int i = 0; i < 4; ++i) {
        m_i[i] = -1e30f;
        l_i[i] = 0.0f;
        o2[i][0] = 0ull;
        o2[i][1] = 0ull;
    }

    const size_t kvhead = (size_t)bh * S_ * HD_;

    for (int kt = 0; kt < S_ / 64; ++kt) {
        const size_t kb = kvhead + (size_t)kt * 64 * HD_;

        // prefetch K,V tiles to regs (overlaps with the barrier below)
        float4 kr[4], vr[4];
        int si_[4], e4_[4];
#pragma unroll
        for (int l = 0; l < 4; ++l) {
            int f4 = tid + 256 * l;
            si_[l] = f4 >> 4;
            e4_[l] = (f4 & 15) * 4;
            kr[l] = *reinterpret_cast<const float4*>(&K[kb + (size_t)si_[l] * HD_ + e4_[l]]);
            vr[l] = *reinterpret_cast<const float4*>(&V[kb + (size_t)si_[l] * HD_ + e4_[l]]);
        }
        __syncthreads();   // previous PV done reading Ks/Vs
#pragma unroll
        for (int l = 0; l < 4; ++l) {
            *reinterpret_cast<float4*>(&Ks[si_[l] * TSTR + e4_[l]]) = kr[l];
            *reinterpret_cast<float4*>(&Vs[si_[l] * TSTR + e4_[l]]) = vr[l];
        }
        __syncthreads();   // tiles visible

        // ---- scores: e-paired FFMA2, fold at end ----
        u64 s2[4][4];
#pragma unroll
        for (int i = 0; i < 4; ++i)
#pragma unroll
            for (int j = 0; j < 4; ++j) s2[i][j] = 0ull;

#pragma unroll 4
        for (int e4 = 0; e4 < HD_; e4 += 4) {
            ulonglong2 a[4], c[4];
#pragma unroll
            for (int i = 0; i < 4; ++i)
                a[i] = *reinterpret_cast<const ulonglong2*>(&Qs[(4 * ty + i) * TSTR + e4]);
#pragma unroll
            for (int j = 0; j < 4; ++j)
                c[j] = *reinterpret_cast<const ulonglong2*>(&Ks[(tx + 16 * j) * TSTR + e4]);
#pragma unroll
            for (int i = 0; i < 4; ++i)
#pragma unroll
                for (int j = 0; j < 4; ++j) {
                    s2[i][j] = ffma2(a[i].x, c[j].x, s2[i][j]);
                    s2[i][j] = ffma2(a[i].y, c[j].y, s2[i][j]);
                }
        }

        // ---- online softmax ----
#pragma unroll
        for (int i = 0; i < 4; ++i) {
            float sc0 = fold2(s2[i][0]) * 0.125f;
            float sc1 = fold2(s2[i][1]) * 0.125f;
            float sc2 = fold2(s2[i][2]) * 0.125f;
            float sc3 = fold2(s2[i][3]) * 0.125f;
            float mx = fmaxf(fmaxf(sc0, sc1), fmaxf(sc2, sc3));
#pragma unroll
            for (int off = 1; off < 16; off <<= 1)
                mx = fmaxf(mx, __shfl_xor_sync(0xffffffffu, mx, off, 16));
            float mn = fmaxf(m_i[i], mx);
            float corr = fast_exp(m_i[i] - mn);
            float p0 = fast_exp(sc0 - mn);
            float p1 = fast_exp(sc1 - mn);
            float p2 = fast_exp(sc2 - mn);
            float p3 = fast_exp(sc3 - mn);
            float rs = p0 + p1 + p2 + p3;
#pragma unroll
            for (int off = 1; off < 16; off <<= 1)
                rs += __shfl_xor_sync(0xffffffffu, rs, off, 16);
            l_i[i] = l_i[i] * corr + rs;
            u64 c2 = dup2(corr);
            o2[i][0] = fmul2(o2[i][0], c2);
            o2[i][1] = fmul2(o2[i][1], c2);
            m_i[i] = mn;
            // duplicated P store: one STS.64 per (row,col)
            int rbase = (4 * ty + i) * PSTR;
            *reinterpret_cast<u64*>(&Psd[rbase + 2 * (tx + 0)])  = dup2(p0);
            *reinterpret_cast<u64*>(&Psd[rbase + 2 * (tx + 16)]) = dup2(p1);
            *reinterpret_cast<u64*>(&Psd[rbase + 2 * (tx + 32)]) = dup2(p2);
            *reinterpret_cast<u64*>(&Psd[rbase + 2 * (tx + 48)]) = dup2(p3);
        }
        __syncwarp();   // P rows are warp-private (same-ty threads share a warp)

        // ---- O += P @ V  (c-paired FFMA2; dup'd P, natural V) ----
#pragma unroll 4
        for (int c = 0; c < 64; c += 4) {
            ulonglong2 v[4];
#pragma unroll
            for (int cp = 0; cp < 4; ++cp)
                v[cp] = *reinterpret_cast<const ulonglong2*>(&Vs[(c + cp) * TSTR + 4 * tx]);
#pragma unroll
            for (int i = 0; i < 4; ++i) {
                int rbase = (4 * ty + i) * PSTR + 2 * c;
                ulonglong2 p01 = *reinterpret_cast<const ulonglong2*>(&Psd[rbase]);
                ulonglong2 p23 = *reinterpret_cast<const ulonglong2*>(&Psd[rbase + 4]);
                o2[i][0] = ffma2(p01.x, v[0].x, o2[i][0]);
                o2[i][1] = ffma2(p01.x, v[0].y, o2[i][1]);
                o2[i][0] = ffma2(p01.y, v[1].x, o2[i][0]);
                o2[i][1] = ffma2(p01.y, v[1].y, o2[i][1]);
                o2[i][0] = ffma2(p23.x, v[2].x, o2[i][0]);
                o2[i][1] = ffma2(p23.x, v[2].y, o2[i][1]);
                o2[i][0] = ffma2(p23.y, v[3].x, o2[i][0]);
                o2[i][1] = ffma2(p23.y, v[3].y, o2[i][1]);
            }
        }
    }

    // ---- epilogue ----
    const int bb = bh >> 4;
    const int hh = bh & 15;
#pragma unroll
    for (int i = 0; i < 4; ++i) {
        float inv = 1.0f / l_i[i];
        int ss = qt * 64 + 4 * ty + i;
        size_t base = ((size_t)bb * S_ + ss) * D_ + hh * HD_ + 4 * tx;
        float4 v;
        v.x = lo32(o2[i][0]) * inv;
        v.y = hi32(o2[i][0]) * inv;
        v.z = lo32(o2[i][1]) * inv;
        v.w = hi32(o2[i][1]) * inv;
        *reinterpret_cast<float4*>(&ctx[base]) = v;
    }
}

// ---------------------------------------------------------------------------
// Launch
// ---------------------------------------------------------------------------
extern "C" void kernel_launch(void* const* d_in, const int* in_sizes, int n_in,
                              void* d_out, int out_size) {
    const float* x  = (const float*)d_in[0];
    const float* Wq = (const float*)d_in[1];
    const float* bq = (const float*)d_in[2];
    const float* Wk = (const float*)d_in[3];
    const float* bk = (const float*)d_in[4];
    const float* Wv = (const float*)d_in[5];
    const float* bv = (const float*)d_in[6];
    const float* Wo = (const float*)d_in[7];
    const float* bo = (const float*)d_in[8];
    float* out = (float*)d_out;

    float *Qp, *Kp, *Vp, *Cp;
    cudaGetSymbolAddress((void**)&Qp, g_Q);
    cudaGetSymbolAddress((void**)&Kp, g_K);
    cudaGetSymbolAddress((void**)&Vp, g_V);
    cudaGetSymbolAddress((void**)&Cp, g_ctx);

    cudaFuncSetAttribute(attn_kernel,
                         cudaFuncAttributeMaxDynamicSharedMemorySize, ATT_SMEM);

    dim3 gproj(D_ / 64, M_ / 64);
    gemm_kernel<<<gproj, 256>>>(x, Wq, bq, Qp, 1);
    gemm_kernel<<<gproj, 256>>>(x, Wk, bk, Kp, 1);
    gemm_kernel<<<gproj, 256>>>(x, Wv, bv, Vp, 1);

    attn_kernel<<<dim3(S_ / 64, B_ * H_), 256, ATT_SMEM>>>(Qp, Kp, Vp, Cp);

    gemm_kernel<<<gproj, 256>>>(Cp, Wo, bo, out, 0);
}

// round 4
// speedup vs baseline: 2.8410x; 2.6808x over previous
#include <cuda_runtime.h>
#include <cuda_bf16.h>
#include <cstdint>
#include <cstddef>

// Problem constants
#define B_  2
#define S_  2048
#define D_  1024
#define H_  16
#define HD_ 64
#define M_  (B_ * S_)

typedef unsigned long long u64;
typedef unsigned int u32;

// Scratch (device globals; no allocation allowed)
__device__ float g_Q[(size_t)B_ * H_ * S_ * HD_];   // [bh][s][e]
__device__ float g_K[(size_t)B_ * H_ * S_ * HD_];
__device__ float g_V[(size_t)B_ * H_ * S_ * HD_];
__device__ float g_ctx[(size_t)B_ * S_ * D_];       // [b][s][h*64+e]

// ---------------------------------------------------------------------------
// Helpers
// ---------------------------------------------------------------------------
__device__ __forceinline__ u32 smem_u32(const void* p) {
    u32 a;
    asm("{ .reg .u64 t; cvta.to.shared.u64 t, %1; cvt.u32.u64 %0, t; }"
        : "=r"(a) : "l"(p));
    return a;
}
__device__ __forceinline__ u32 tf32r(float f) {
    u32 r;
    asm("cvt.rna.tf32.f32 %0, %1;" : "=r"(r) : "f"(f));
    return r;
}
__device__ __forceinline__ float tf32f(float f) {
    return __uint_as_float(tf32r(f));
}

// m16n8k8 tf32 MMA, D==C in place.
__device__ __forceinline__ void mma8(float d[4], const u32 a[4], u32 b0, u32 b1) {
    asm volatile(
        "mma.sync.aligned.m16n8k8.row.col.f32.tf32.tf32.f32 "
        "{%0,%1,%2,%3}, {%4,%5,%6,%7}, {%8,%9}, {%0,%1,%2,%3};"
        : "+f"(d[0]), "+f"(d[1]), "+f"(d[2]), "+f"(d[3])
        : "r"(a[0]), "r"(a[1]), "r"(a[2]), "r"(a[3]), "r"(b0), "r"(b1));
}

__device__ __forceinline__ void cp_async16(u32 dst, const void* src) {
    asm volatile("cp.async.cg.shared.global [%0], [%1], 16;" :: "r"(dst), "l"(src));
}
__device__ __forceinline__ void cp_commit() {
    asm volatile("cp.async.commit_group;");
}
template <int N> __device__ __forceinline__ void cp_wait() {
    asm volatile("cp.async.wait_group %0;" :: "n"(N));
}

// FMA-pipe exp (avoids MUFU wall; x <= 0 path)
__device__ __forceinline__ float fast_exp(float x) {
    float t = fmaxf(x * 1.4426950408889634f, -60.0f);
    float n = rintf(t);
    float f = t - n;
    float u = f * 0.6931471805599453f;
    float p = fmaf(u, 0.0416666679f, 0.1666666667f);
    p = fmaf(p, u, 0.5f);
    p = fmaf(p, u, 1.0f);
    p = fmaf(p, u, 1.0f);
    int e = (((int)n) + 127) << 23;
    return __int_as_float(e) * p;
}

// ---------------------------------------------------------------------------
// GEMM (mma.sync tf32): out[4096, N] = X[4096,1024] @ W + bias
// BM=128, BN=64, BK=32, 256 threads, 8 warps (4m x 2n), warp tile 32x32.
// A: cp.async double-buffered, fp32 in smem, tf32-cvt at fragment load.
// B: LDG->cvt->STS transposed [n][k], tf32 in smem.
// headstack=1: W=[H,1024,64], head = blockIdx.y, out -> [bh][s][e]
// headstack=0: W=[1024,1024], out row-major, n0 = blockIdx.y*64
// ---------------------------------------------------------------------------
#define BM 128
#define BN 64
#define BK 32
#define NCH (D_ / BK)
#define GSTR 36
#define AS_FLOATS (BM * GSTR)
#define BS_FLOATS (BN * GSTR)
#define BUF_FLOATS (AS_FLOATS + BS_FLOATS)
#define GEMM_SMEM (2 * BUF_FLOATS * 4)

__global__ __launch_bounds__(256) void gemm_tc(const float* __restrict__ X,
                                               const float* __restrict__ W,
                                               const float* __restrict__ bias,
                                               float* __restrict__ out,
                                               int headstack) {
    extern __shared__ float sm[];
    __shared__ float s_bias[64];

    const int tid = threadIdx.x;
    const int lane = tid & 31, wid = tid >> 5;
    const int gid = lane >> 2, tig = lane & 3;
    const int wm = wid & 3, wn = wid >> 2;
    const int mt0 = blockIdx.x * BM;
    const int nh = blockIdx.y;

    const float* Wb = headstack ? (W + (size_t)nh * (D_ * HD_)) : (W + nh * BN);
    const int ldw = headstack ? HD_ : D_;
    const float* bp = headstack ? (bias + nh * HD_) : (bias + nh * BN);
    if (tid < 64) s_bias[tid] = bp[tid];

    const u32 smb = smem_u32(sm);
    const int nn = tid & 63;          // B col
    const int kq = tid >> 6;          // B k phase (0..3)

    float acc[2][4][4] = {};

    float breg[8];
#pragma unroll
    for (int j = 0; j < 8; ++j)
        breg[j] = Wb[(size_t)(kq + 4 * j) * ldw + nn];
#pragma unroll
    for (int l = 0; l < 4; ++l) {
        int idx = tid + 256 * l, row = idx >> 3, c4 = (idx & 7) * 4;
        cp_async16(smb + (u32)(row * GSTR + c4) * 4,
                   &X[(size_t)(mt0 + row) * D_ + c4]);
    }
    cp_commit();

    for (int c = 0; c < NCH; ++c) {
        const int b = c & 1;
        float* BsW = sm + b * BUF_FLOATS + AS_FLOATS;
#pragma unroll
        for (int j = 0; j < 8; ++j)
            BsW[nn * GSTR + kq + 4 * j] = tf32f(breg[j]);

        if (c + 1 < NCH) {
            const int k0 = (c + 1) * BK;
#pragma unroll
            for (int j = 0; j < 8; ++j)
                breg[j] = Wb[(size_t)(k0 + kq + 4 * j) * ldw + nn];
            const u32 ab = smb + (u32)((1 - b) * BUF_FLOATS) * 4;
#pragma unroll
            for (int l = 0; l < 4; ++l) {
                int idx = tid + 256 * l, row = idx >> 3, c4 = (idx & 7) * 4;
                cp_async16(ab + (u32)(row * GSTR + c4) * 4,
                           &X[(size_t)(mt0 + row) * D_ + k0 + c4]);
            }
            cp_commit();
            cp_wait<1>();
        } else {
            cp_wait<0>();
        }
        __syncthreads();

        const float* As = sm + b * BUF_FLOATS;
        const float* Bs = sm + b * BUF_FLOATS + AS_FLOATS;
#pragma unroll
        for (int ks = 0; ks < 4; ++ks) {
            u32 a[2][4];
#pragma unroll
            for (int mt = 0; mt < 2; ++mt) {
                int r = wm * 32 + mt * 16 + gid;
                a[mt][0] = tf32r(As[r * GSTR + ks * 8 + tig]);
                a[mt][1] = tf32r(As[(r + 8) * GSTR + ks * 8 + tig]);
                a[mt][2] = tf32r(As[r * GSTR + ks * 8 + tig + 4]);
                a[mt][3] = tf32r(As[(r + 8) * GSTR + ks * 8 + tig + 4]);
            }
#pragma unroll
            for (int nt = 0; nt < 4; ++nt) {
                int nr = wn * 32 + nt * 8 + gid;
                u32 b0 = __float_as_uint(Bs[nr * GSTR + ks * 8 + tig]);
                u32 b1 = __float_as_uint(Bs[nr * GSTR + ks * 8 + tig + 4]);
                mma8(acc[0][nt], a[0], b0, b1);
                mma8(acc[1][nt], a[1], b0, b1);
            }
        }
        __syncthreads();
    }

    // epilogue
#pragma unroll
    for (int mt = 0; mt < 2; ++mt) {
#pragma unroll
        for (int rr = 0; rr < 2; ++rr) {
            int m = mt0 + wm * 32 + mt * 16 + gid + rr * 8;
            float* dst;
            if (headstack) {
                int bb = m >> 11, ss = m & (S_ - 1);
                dst = out + ((size_t)(bb * H_ + nh) * S_ + ss) * HD_;
            } else {
                dst = out + (size_t)m * D_ + nh * BN;
            }
#pragma unroll
            for (int nt = 0; nt < 4; ++nt) {
                int colw = wn * 32 + nt * 8 + 2 * tig;
                float2 v;
                v.x = acc[mt][nt][2 * rr + 0] + s_bias[colw];
                v.y = acc[mt][nt][2 * rr + 1] + s_bias[colw + 1];
                *reinterpret_cast<float2*>(&dst[colw]) = v;
            }
        }
    }
}

// ---------------------------------------------------------------------------
// Flash attention (mma.sync tf32, FA2 layout).
// Block = 128 q-rows of one (b,h); 8 warps x 16 rows. Grid (16, 32).
// Q pre-scaled (1/8) persistent tf32 a-frags. K,V tf32 in smem.
// Softmax on C-frag layout; P permuted C->A frags via intra-quad shuffles.
// ---------------------------------------------------------------------------
#define KSTR 68
#define VSTR 72
#define ATT_SMEM ((64 * KSTR + 64 * VSTR) * 4)

__global__ __launch_bounds__(256) void attn_tc(const float* __restrict__ Q,
                                               const float* __restrict__ K,
                                               const float* __restrict__ V,
                                               float* __restrict__ ctx) {
    extern __shared__ float sm[];
    float* Ks = sm;                 // [64][KSTR]
    float* Vs = sm + 64 * KSTR;     // [64][VSTR]

    const int tid = threadIdx.x, lane = tid & 31, wid = tid >> 5;
    const int gid = lane >> 2, tig = lane & 3;
    const int qt = blockIdx.x, bh = blockIdx.y;

    // stage Q tile [128][64] into smem (fits in Ks+Vs region: 128*KSTR < total)
    const size_t qbase = ((size_t)bh * S_ + qt * 128) * HD_;
#pragma unroll
    for (int l = 0; l < 8; ++l) {
        int idx = tid + 256 * l, row = idx >> 4, c4 = (idx & 15) * 4;
        *reinterpret_cast<float4*>(&sm[row * KSTR + c4]) =
            *reinterpret_cast<const float4*>(&Q[qbase + (size_t)row * HD_ + c4]);
    }
    __syncthreads();

    u32 qa[8][4];
    {
        int r = wid * 16 + gid;
#pragma unroll
        for (int ks = 0; ks < 8; ++ks) {
            qa[ks][0] = tf32r(sm[r * KSTR + ks * 8 + tig] * 0.125f);
            qa[ks][1] = tf32r(sm[(r + 8) * KSTR + ks * 8 + tig] * 0.125f);
            qa[ks][2] = tf32r(sm[r * KSTR + ks * 8 + tig + 4] * 0.125f);
            qa[ks][3] = tf32r(sm[(r + 8) * KSTR + ks * 8 + tig + 4] * 0.125f);
        }
    }
    __syncthreads();

    float o[8][4] = {};
    float m[2] = {-1e30f, -1e30f};
    float lsum[2] = {0.0f, 0.0f};
    const size_t kvb = (size_t)bh * S_ * HD_;

    for (int kt = 0; kt < S_ / 64; ++kt) {
        const size_t tb = kvb + (size_t)kt * 64 * HD_;
#pragma unroll
        for (int l = 0; l < 4; ++l) {
            int idx = tid + 256 * l, row = idx >> 4, c4 = (idx & 15) * 4;
            float4 kv = *reinterpret_cast<const float4*>(&K[tb + (size_t)row * HD_ + c4]);
            float4 vv = *reinterpret_cast<const float4*>(&V[tb + (size_t)row * HD_ + c4]);
            kv.x = tf32f(kv.x); kv.y = tf32f(kv.y); kv.z = tf32f(kv.z); kv.w = tf32f(kv.w);
            vv.x = tf32f(vv.x); vv.y = tf32f(vv.y); vv.z = tf32f(vv.z); vv.w = tf32f(vv.w);
            *reinterpret_cast<float4*>(&Ks[row * KSTR + c4]) = kv;
            *reinterpret_cast<float4*>(&Vs[row * VSTR + c4]) = vv;
        }
        __syncthreads();

        // ---- scores S[16q x 64kv] per warp ----
        float s[8][4] = {};
#pragma unroll
        for (int ks = 0; ks < 8; ++ks) {
#pragma unroll
            for (int nt = 0; nt < 8; ++nt) {
                u32 b0 = __float_as_uint(Ks[(nt * 8 + gid) * KSTR + ks * 8 + tig]);
                u32 b1 = __float_as_uint(Ks[(nt * 8 + gid) * KSTR + ks * 8 + tig + 4]);
                mma8(s[nt], qa[ks], b0, b1);
            }
        }

        // ---- online softmax (row stats within 4-lane quads) ----
#pragma unroll
        for (int j = 0; j < 2; ++j) {
            float mx = s[0][2 * j];
#pragma unroll
            for (int nt = 0; nt < 8; ++nt) {
                mx = fmaxf(mx, s[nt][2 * j]);
                mx = fmaxf(mx, s[nt][2 * j + 1]);
            }
            mx = fmaxf(mx, __shfl_xor_sync(0xffffffffu, mx, 1));
            mx = fmaxf(mx, __shfl_xor_sync(0xffffffffu, mx, 2));
            float mn = fmaxf(m[j], mx);
            float corr = fast_exp(m[j] - mn);
            m[j] = mn;
            float sum = 0.0f;
#pragma unroll
            for (int nt = 0; nt < 8; ++nt) {
                float p0 = fast_exp(s[nt][2 * j] - mn);
                float p1 = fast_exp(s[nt][2 * j + 1] - mn);
                s[nt][2 * j] = p0;
                s[nt][2 * j + 1] = p1;
                sum += p0 + p1;
            }
            sum += __shfl_xor_sync(0xffffffffu, sum, 1);
            sum += __shfl_xor_sync(0xffffffffu, sum, 2);
            lsum[j] = lsum[j] * corr + sum;
#pragma unroll
            for (int nt = 0; nt < 8; ++nt) {
                o[nt][2 * j] *= corr;
                o[nt][2 * j + 1] *= corr;
            }
        }

        // ---- O += P @ V : permute P C-frag -> A-frag via quad shuffles ----
#pragma unroll
        for (int ks = 0; ks < 8; ++ks) {
            int src = (lane & ~3) | (tig >> 1);
            float v00 = __shfl_sync(0xffffffffu, s[ks][0], src);
            float v01 = __shfl_sync(0xffffffffu, s[ks][1], src);
            float v10 = __shfl_sync(0xffffffffu, s[ks][2], src);
            float v11 = __shfl_sync(0xffffffffu, s[ks][3], src);
            float w00 = __shfl_sync(0xffffffffu, s[ks][0], src + 2);
            float w01 = __shfl_sync(0xffffffffu, s[ks][1], src + 2);
            float w10 = __shfl_sync(0xffffffffu, s[ks][2], src + 2);
            float w11 = __shfl_sync(0xffffffffu, s[ks][3], src + 2);
            bool odd = (tig & 1) != 0;
            u32 pa[4];
            pa[0] = tf32r(odd ? v01 : v00);
            pa[1] = tf32r(odd ? v11 : v10);
            pa[2] = tf32r(odd ? w01 : w00);
            pa[3] = tf32r(odd ? w11 : w10);
#pragma unroll
            for (int nte = 0; nte < 8; ++nte) {
                u32 b0 = __float_as_uint(Vs[(ks * 8 + tig) * VSTR + nte * 8 + gid]);
                u32 b1 = __float_as_uint(Vs[(ks * 8 + tig + 4) * VSTR + nte * 8 + gid]);
                mma8(o[nte], pa, b0, b1);
            }
        }
        __syncthreads();
    }

    // ---- epilogue: normalize, write ctx[b][s][h*64+e] ----
    const int bb = bh >> 4, hh = bh & 15;
#pragma unroll
    for (int j = 0; j < 2; ++j) {
        float inv = 1.0f / lsum[j];
        int srow = qt * 128 + wid * 16 + gid + 8 * j;
        size_t base = ((size_t)bb * S_ + srow) * D_ + hh * HD_;
#pragma unroll
        for (int nte = 0; nte < 8; ++nte) {
            float2 v;
            v.x = o[nte][2 * j] * inv;
            v.y = o[nte][2 * j + 1] * inv;
            *reinterpret_cast<float2*>(&ctx[base + nte * 8 + 2 * tig]) = v;
        }
    }
}

// ---------------------------------------------------------------------------
// Launch
// ---------------------------------------------------------------------------
extern "C" void kernel_launch(void* const* d_in, const int* in_sizes, int n_in,
                              void* d_out, int out_size) {
    const float* x  = (const float*)d_in[0];
    const float* Wq = (const float*)d_in[1];
    const float* bq = (const float*)d_in[2];
    const float* Wk = (const float*)d_in[3];
    const float* bk = (const float*)d_in[4];
    const float* Wv = (const float*)d_in[5];
    const float* bv = (const float*)d_in[6];
    const float* Wo = (const float*)d_in[7];
    const float* bo = (const float*)d_in[8];
    float* out = (float*)d_out;

    float *Qp, *Kp, *Vp, *Cp;
    cudaGetSymbolAddress((void**)&Qp, g_Q);
    cudaGetSymbolAddress((void**)&Kp, g_K);
    cudaGetSymbolAddress((void**)&Vp, g_V);
    cudaGetSymbolAddress((void**)&Cp, g_ctx);

    cudaFuncSetAttribute(gemm_tc,
                         cudaFuncAttributeMaxDynamicSharedMemorySize, GEMM_SMEM);
    cudaFuncSetAttribute(attn_tc,
                         cudaFuncAttributeMaxDynamicSharedMemorySize, ATT_SMEM);

    dim3 g(M_ / BM, H_);   // (32, 16)
    gemm_tc<<<g, 256, GEMM_SMEM>>>(x, Wq, bq, Qp, 1);
    gemm_tc<<<g, 256, GEMM_SMEM>>>(x, Wk, bk, Kp, 1);
    gemm_tc<<<g, 256, GEMM_SMEM>>>(x, Wv, bv, Vp, 1);

    attn_tc<<<dim3(S_ / 128, B_ * H_), 256, ATT_SMEM>>>(Qp, Kp, Vp, Cp);

    gemm_tc<<<g, 256, GEMM_SMEM>>>(Cp, Wo, bo, out, 0);
}

// round 5
// speedup vs baseline: 6.3754x; 2.2441x over previous
#include <cuda_runtime.h>
#include <cuda_fp16.h>
#include <cstdint>
#include <cstddef>

// Problem constants
#define B_  2
#define S_  2048
#define D_  1024
#define H_  16
#define HD_ 64
#define M_  (B_ * S_)

typedef unsigned long long u64;
typedef unsigned int u32;

#define NX 4194304   // X elements (4096*1024)
#define NW 1048576   // each weight tensor (16*1024*64 or 1024*1024)

// fp16 scratch (device globals; no allocation allowed)
__device__ __align__(16) __half g_Xh[NX];
__device__ __align__(16) __half g_Wqh[NW];
__device__ __align__(16) __half g_Wkh[NW];
__device__ __align__(16) __half g_Wvh[NW];
__device__ __align__(16) __half g_Woh[NW];
__device__ __align__(16) __half g_Qh[NX / 1];   // [bh][s][e] : 4.19M halves
__device__ __align__(16) __half g_Kh[NX];
__device__ __align__(16) __half g_Vh[NX];
__device__ __align__(16) __half g_ctxh[NX];     // [b][s][h*64+e]

// ---------------------------------------------------------------------------
// PTX helpers
// ---------------------------------------------------------------------------
__device__ __forceinline__ u32 smem_u32(const void* p) {
    u32 a;
    asm("{ .reg .u64 t; cvta.to.shared.u64 t, %1; cvt.u32.u64 %0, t; }"
        : "=r"(a) : "l"(p));
    return a;
}
__device__ __forceinline__ void ldm_x4(u32 r[4], u32 a) {
    asm volatile("ldmatrix.sync.aligned.m8n8.x4.shared.b16 {%0,%1,%2,%3}, [%4];"
                 : "=r"(r[0]), "=r"(r[1]), "=r"(r[2]), "=r"(r[3]) : "r"(a));
}
__device__ __forceinline__ void ldm_x4t(u32 r[4], u32 a) {
    asm volatile("ldmatrix.sync.aligned.m8n8.x4.trans.shared.b16 {%0,%1,%2,%3}, [%4];"
                 : "=r"(r[0]), "=r"(r[1]), "=r"(r[2]), "=r"(r[3]) : "r"(a));
}
// m16n8k16 fp16 MMA, fp32 accumulate in place
__device__ __forceinline__ void mma16(float d[4], const u32 a[4], u32 b0, u32 b1) {
    asm volatile(
        "mma.sync.aligned.m16n8k16.row.col.f32.f16.f16.f32 "
        "{%0,%1,%2,%3}, {%4,%5,%6,%7}, {%8,%9}, {%0,%1,%2,%3};"
        : "+f"(d[0]), "+f"(d[1]), "+f"(d[2]), "+f"(d[3])
        : "r"(a[0]), "r"(a[1]), "r"(a[2]), "r"(a[3]), "r"(b0), "r"(b1));
}
// pack two f32 -> f16x2 (lo = first elem, hi = second elem)
__device__ __forceinline__ u32 packh2(float lo, float hi) {
    u32 d;
    asm("cvt.rn.f16x2.f32 %0, %1, %2;" : "=r"(d) : "f"(hi), "f"(lo));
    return d;
}
__device__ __forceinline__ u32 hmul2u(u32 a, u32 b) {
    u32 d;
    asm("mul.rn.f16x2 %0, %1, %2;" : "=r"(d) : "r"(a), "r"(b));
    return d;
}
__device__ __forceinline__ void cp_async16(u32 dst, const void* src) {
    asm volatile("cp.async.cg.shared.global [%0], [%1], 16;" :: "r"(dst), "l"(src));
}
__device__ __forceinline__ void cp_commit() {
    asm volatile("cp.async.commit_group;");
}
template <int N> __device__ __forceinline__ void cp_wait() {
    asm volatile("cp.async.wait_group %0;" :: "n"(N));
}

// FMA-pipe exp (avoids MUFU wall; x <= 0 path)
__device__ __forceinline__ float fast_exp(float x) {
    float t = fmaxf(x * 1.4426950408889634f, -60.0f);
    float n = rintf(t);
    float f = t - n;
    float u = f * 0.6931471805599453f;
    float p = fmaf(u, 0.0416666679f, 0.1666666667f);
    p = fmaf(p, u, 0.5f);
    p = fmaf(p, u, 1.0f);
    p = fmaf(p, u, 1.0f);
    int e = (((int)n) + 127) << 23;
    return __int_as_float(e) * p;
}

// ---------------------------------------------------------------------------
// fp32 -> fp16 conversion prep (X, Wq, Wk, Wv, Wo)
// ---------------------------------------------------------------------------
__global__ __launch_bounds__(256) void cvt_all(const float* __restrict__ x,
                                               const float* __restrict__ wq,
                                               const float* __restrict__ wk,
                                               const float* __restrict__ wv,
                                               const float* __restrict__ wo) {
    const int i4 = (blockIdx.x * 256 + threadIdx.x) * 4;
    const float* src;
    __half* dst;
    if (i4 < NX) {
        src = x + i4; dst = g_Xh + i4;
    } else {
        int j = i4 - NX;
        int w = j >> 20;          // / NW
        int off = j & (NW - 1);
        if (w == 0)      { src = wq + off; dst = g_Wqh + off; }
        else if (w == 1) { src = wk + off; dst = g_Wkh + off; }
        else if (w == 2) { src = wv + off; dst = g_Wvh + off; }
        else             { src = wo + off; dst = g_Woh + off; }
    }
    float4 v = *reinterpret_cast<const float4*>(src);
    uint2 o;
    o.x = packh2(v.x, v.y);
    o.y = packh2(v.z, v.w);
    *reinterpret_cast<uint2*>(dst) = o;
}

// ---------------------------------------------------------------------------
// fp16 GEMM core: acc[2][4][4] += A[m0:m0+128, :1024] @ W[:, n-slice 64]
// BM=128, BN=64, BK=64. 256 threads, 8 warps (4m x 2n), warp tile 32x32.
// A [m][k] smem (ldmatrix), W [k][n] smem (ldmatrix.trans). cp.async db-buf.
// ---------------------------------------------------------------------------
#define ASTR 72
#define BSTR 72
#define AS_H (128 * ASTR)
#define BS_H (64 * BSTR)
#define NCH  (D_ / 64)
#define GEMM_SMEM ((2 * AS_H + 2 * BS_H) * 2)

__device__ __forceinline__ void gemm_core(const __half* __restrict__ A,
                                          const __half* __restrict__ Wb,
                                          int ldw, int m0, __half* sm,
                                          float acc[2][4][4]) {
    const int tid = threadIdx.x, lane = tid & 31, wid = tid >> 5;
    const int wm = wid & 3, wn = wid >> 2;
    const u32 AsU[2] = {smem_u32(sm), smem_u32(sm + AS_H)};
    const u32 BsU[2] = {smem_u32(sm + 2 * AS_H), smem_u32(sm + 2 * AS_H + BS_H)};

    const u32 a_l = (u32)((((lane & 7) + ((lane >> 3) & 1) * 8 + wm * 32) * ASTR
                           + (lane >> 4) * 8) * 2);
    const u32 b_l = (u32)((((lane & 7) + ((lane >> 3) & 1) * 8) * BSTR
                           + wn * 32 + (lane >> 4) * 8) * 2);

#define GPREF(c, buf) do {                                                    \
        const int _k0 = (c) * 64;                                             \
        _Pragma("unroll")                                                     \
        for (int l = 0; l < 4; ++l) {                                         \
            int idx = tid + 256 * l, row = idx >> 3, cc = idx & 7;            \
            cp_async16(AsU[buf] + (u32)((row * ASTR + cc * 8) * 2),           \
                       A + (size_t)(m0 + row) * D_ + _k0 + cc * 8);           \
        }                                                                     \
        _Pragma("unroll")                                                     \
        for (int l = 0; l < 2; ++l) {                                         \
            int idx = tid + 256 * l, row = idx >> 3, cc = idx & 7;            \
            cp_async16(BsU[buf] + (u32)((row * BSTR + cc * 8) * 2),           \
                       Wb + (size_t)(_k0 + row) * ldw + cc * 8);              \
        }                                                                     \
        cp_commit();                                                          \
    } while (0)

    GPREF(0, 0);
    for (int c = 0; c < NCH; ++c) {
        const int buf = c & 1;
        if (c + 1 < NCH) { GPREF(c + 1, buf ^ 1); cp_wait<1>(); }
        else             { cp_wait<0>(); }
        __syncthreads();
#pragma unroll
        for (int ks = 0; ks < 4; ++ks) {
            u32 a[2][4];
#pragma unroll
            for (int mt = 0; mt < 2; ++mt)
                ldm_x4(a[mt], AsU[buf] + a_l + (u32)((mt * 16 * ASTR + ks * 16) * 2));
#pragma unroll
            for (int np = 0; np < 2; ++np) {
                u32 b4[4];
                ldm_x4t(b4, BsU[buf] + b_l + (u32)((ks * 16 * BSTR + np * 16) * 2));
                mma16(acc[0][2 * np],     a[0], b4[0], b4[1]);
                mma16(acc[0][2 * np + 1], a[0], b4[2], b4[3]);
                mma16(acc[1][2 * np],     a[1], b4[0], b4[1]);
                mma16(acc[1][2 * np + 1], a[1], b4[2], b4[3]);
            }
        }
        __syncthreads();
    }
#undef GPREF
}

// QKV merged: grid (32, 48); y = proj*16 + head. Output fp16 [bh][s][e].
__global__ __launch_bounds__(256, 2) void gemm_qkv(const float* __restrict__ bq,
                                                   const float* __restrict__ bk,
                                                   const float* __restrict__ bv) {
    extern __shared__ __half sm[];
    const int tid = threadIdx.x, lane = tid & 31, wid = tid >> 5;
    const int gid = lane >> 2, tig = lane & 3;
    const int wm = wid & 3, wn = wid >> 2;
    const int m0 = blockIdx.x * 128;
    const int proj = blockIdx.y >> 4;
    const int head = blockIdx.y & 15;

    const __half* Wsel = (proj == 0 ? g_Wqh : proj == 1 ? g_Wkh : g_Wvh)
                         + (size_t)head * (D_ * HD_);
    const float* bsel = (proj == 0 ? bq : proj == 1 ? bk : bv) + head * HD_;
    __half* osel = (proj == 0 ? g_Qh : proj == 1 ? g_Kh : g_Vh);

    float acc[2][4][4] = {};
    gemm_core(g_Xh, Wsel, HD_, m0, sm, acc);

#pragma unroll
    for (int mt = 0; mt < 2; ++mt) {
#pragma unroll
        for (int rr = 0; rr < 2; ++rr) {
            int m = m0 + wm * 32 + mt * 16 + gid + rr * 8;
            int bb = m >> 11, ss = m & (S_ - 1);
            __half* dst = osel + ((size_t)(bb * H_ + head) * S_ + ss) * HD_;
#pragma unroll
            for (int nt = 0; nt < 4; ++nt) {
                int col = wn * 32 + nt * 8 + 2 * tig;
                float v0 = acc[mt][nt][2 * rr]     + bsel[col];
                float v1 = acc[mt][nt][2 * rr + 1] + bsel[col + 1];
                *reinterpret_cast<u32*>(dst + col) = packh2(v0, v1);
            }
        }
    }
}

// Output projection: grid (32, 16); fp32 output + bias.
__global__ __launch_bounds__(256, 2) void gemm_out(const float* __restrict__ bo,
                                                   float* __restrict__ out) {
    extern __shared__ __half sm[];
    const int tid = threadIdx.x, lane = tid & 31, wid = tid >> 5;
    const int gid = lane >> 2, tig = lane & 3;
    const int wm = wid & 3, wn = wid >> 2;
    const int m0 = blockIdx.x * 128;
    const int n0 = blockIdx.y * 64;

    float acc[2][4][4] = {};
    gemm_core(g_ctxh, g_Woh + n0, D_, m0, sm, acc);

#pragma unroll
    for (int mt = 0; mt < 2; ++mt) {
#pragma unroll
        for (int rr = 0; rr < 2; ++rr) {
            int m = m0 + wm * 32 + mt * 16 + gid + rr * 8;
            float* dst = out + (size_t)m * D_ + n0;
#pragma unroll
            for (int nt = 0; nt < 4; ++nt) {
                int col = wn * 32 + nt * 8 + 2 * tig;
                float2 v;
                v.x = acc[mt][nt][2 * rr]     + bo[n0 + col];
                v.y = acc[mt][nt][2 * rr + 1] + bo[n0 + col + 1];
                *reinterpret_cast<float2*>(dst + col) = v;
            }
        }
    }
}

// ---------------------------------------------------------------------------
// Flash attention, fp16 m16n8k16 + ldmatrix, FA2 C->A identity (no shuffles).
// Block = 128 q-rows of one (b,h); 8 warps x 16 rows. Grid (16, 32).
// kv tile = 64. K/V double-buffered via cp.async.
// ---------------------------------------------------------------------------
#define KVSTR 72
#define KV_H (64 * KVSTR)               // halves per tile buffer
#define ATT_SMEM (4 * KV_H * 2)         // K0,K1,V0,V1 = 36864 bytes

__global__ __launch_bounds__(256, 2) void attn_h(const __half* __restrict__ Q,
                                                 const __half* __restrict__ K,
                                                 const __half* __restrict__ V,
                                                 __half* __restrict__ ctx) {
    extern __shared__ __half hsm[];
    const int tid = threadIdx.x, lane = tid & 31, wid = tid >> 5;
    const int gid = lane >> 2, tig = lane & 3;
    const int qt = blockIdx.x, bh = blockIdx.y;

    const u32 KbU[2] = {smem_u32(hsm), smem_u32(hsm + KV_H)};
    const u32 VbU[2] = {smem_u32(hsm + 2 * KV_H), smem_u32(hsm + 3 * KV_H)};

    // ---- stage Q tile [128][64] -> smem (reuses K buffers), build a-frags ---
    const size_t qbase = ((size_t)bh * S_ + qt * 128) * HD_;
#pragma unroll
    for (int l = 0; l < 4; ++l) {
        int idx = tid + 256 * l, row = idx >> 3, cc = idx & 7;
        *reinterpret_cast<uint4*>(&hsm[row * KVSTR + cc * 8]) =
            *reinterpret_cast<const uint4*>(&Q[qbase + (size_t)row * HD_ + cc * 8]);
    }
    __syncthreads();
    u32 qa[4][4];
    {
        const u32 q_l = (u32)(((wid * 16 + (lane & 7) + ((lane >> 3) & 1) * 8) * KVSTR
                               + (lane >> 4) * 8) * 2);
#pragma unroll
        for (int ks = 0; ks < 4; ++ks) {
            ldm_x4(qa[ks], KbU[0] + q_l + (u32)(ks * 16 * 2));
#pragma unroll
            for (int r = 0; r < 4; ++r)
                qa[ks][r] = hmul2u(qa[ks][r], 0x30003000u);   // * 0.125 (exact)
        }
    }
    __syncthreads();

    // ---- fragment lane offsets (bytes, within a tile buffer) ----
    const u32 k_l = (u32)((((lane & 7) + ((lane >> 4) & 1) * 8) * KVSTR
                           + ((lane >> 3) & 1) * 8) * 2);
    const u32 v_l = (u32)((((lane & 7) + ((lane >> 3) & 1) * 8) * KVSTR
                           + (lane >> 4) * 8) * 2);

    const size_t kvb = (size_t)bh * S_ * HD_;
#define APREF(kt, buf) do {                                                   \
        const size_t _tb = kvb + (size_t)(kt) * 64 * HD_;                     \
        _Pragma("unroll")                                                     \
        for (int l = 0; l < 2; ++l) {                                         \
            int idx = tid + 256 * l, row = idx >> 3, cc = idx & 7;            \
            u32 so = (u32)((row * KVSTR + cc * 8) * 2);                       \
            cp_async16(KbU[buf] + so, K + _tb + (size_t)row * HD_ + cc * 8);  \
            cp_async16(VbU[buf] + so, V + _tb + (size_t)row * HD_ + cc * 8);  \
        }                                                                     \
        cp_commit();                                                          \
    } while (0)

    float o[8][4] = {};
    float m[2] = {-1e30f, -1e30f};
    float lsum[2] = {0.0f, 0.0f};

    APREF(0, 0);
    APREF(1, 1);

    for (int kt = 0; kt < 32; ++kt) {
        const int buf = kt & 1;
        if (kt + 1 < 32) cp_wait<1>(); else cp_wait<0>();
        __syncthreads();

        // ---- scores S[16 x 64] ----
        float s[8][4] = {};
#pragma unroll
        for (int ks = 0; ks < 4; ++ks) {
#pragma unroll
            for (int np = 0; np < 4; ++np) {
                u32 kb4[4];
                ldm_x4(kb4, KbU[buf] + k_l
                             + (u32)((np * 16 * KVSTR + ks * 16) * 2));
                mma16(s[2 * np],     qa[ks], kb4[0], kb4[1]);
                mma16(s[2 * np + 1], qa[ks], kb4[2], kb4[3]);
            }
        }

        // ---- online softmax (rows gid / gid+8; cols across tig quads) ----
#pragma unroll
        for (int j = 0; j < 2; ++j) {
            float mx = s[0][2 * j];
#pragma unroll
            for (int nt = 0; nt < 8; ++nt) {
                mx = fmaxf(mx, s[nt][2 * j]);
                mx = fmaxf(mx, s[nt][2 * j + 1]);
            }
            mx = fmaxf(mx, __shfl_xor_sync(0xffffffffu, mx, 1));
            mx = fmaxf(mx, __shfl_xor_sync(0xffffffffu, mx, 2));
            float mn = fmaxf(m[j], mx);
            float corr = fast_exp(m[j] - mn);
            m[j] = mn;
            float sum = 0.0f;
#pragma unroll
            for (int nt = 0; nt < 8; ++nt) {
                float p0 = fast_exp(s[nt][2 * j] - mn);
                float p1 = fast_exp(s[nt][2 * j + 1] - mn);
                s[nt][2 * j] = p0;
                s[nt][2 * j + 1] = p1;
                sum += p0 + p1;
            }
            sum += __shfl_xor_sync(0xffffffffu, sum, 1);
            sum += __shfl_xor_sync(0xffffffffu, sum, 2);
            lsum[j] = lsum[j] * corr + sum;
#pragma unroll
            for (int nt = 0; nt < 8; ++nt) {
                o[nt][2 * j] *= corr;
                o[nt][2 * j + 1] *= corr;
            }
        }

        // ---- O += P @ V : C-frag packs directly into A-frag (FA2 identity) --
#pragma unroll
        for (int ks = 0; ks < 4; ++ks) {
            u32 pa[4];
            pa[0] = packh2(s[2 * ks][0],     s[2 * ks][1]);
            pa[1] = packh2(s[2 * ks][2],     s[2 * ks][3]);
            pa[2] = packh2(s[2 * ks + 1][0], s[2 * ks + 1][1]);
            pa[3] = packh2(s[2 * ks + 1][2], s[2 * ks + 1][3]);
#pragma unroll
            for (int np = 0; np < 4; ++np) {
                u32 vb4[4];
                ldm_x4t(vb4, VbU[buf] + v_l
                              + (u32)((ks * 16 * KVSTR + np * 16) * 2));
                mma16(o[2 * np],     pa, vb4[0], vb4[1]);
                mma16(o[2 * np + 1], pa, vb4[2], vb4[3]);
            }
        }
        __syncthreads();
        if (kt + 2 < 32) APREF(kt + 2, buf);
    }
#undef APREF

    // ---- epilogue: normalize, write fp16 ctx[b][s][h*64+e] ----
    const int bb = bh >> 4, hh = bh & 15;
#pragma unroll
    for (int j = 0; j < 2; ++j) {
        float inv = 1.0f / lsum[j];
        int srow = qt * 128 + wid * 16 + gid + 8 * j;
        __half* dst = ctx + ((size_t)bb * S_ + srow) * D_ + hh * HD_;
#pragma unroll
        for (int nt = 0; nt < 8; ++nt) {
            int col = nt * 8 + 2 * tig;
            *reinterpret_cast<u32*>(dst + col) =
                packh2(o[nt][2 * j] * inv, o[nt][2 * j + 1] * inv);
        }
    }
}

// ---------------------------------------------------------------------------
// Launch
// ---------------------------------------------------------------------------
extern "C" void kernel_launch(void* const* d_in, const int* in_sizes, int n_in,
                              void* d_out, int out_size) {
    const float* x  = (const float*)d_in[0];
    const float* Wq = (const float*)d_in[1];
    const float* bq = (const float*)d_in[2];
    const float* Wk = (const float*)d_in[3];
    const float* bk = (const float*)d_in[4];
    const float* Wv = (const float*)d_in[5];
    const float* bv = (const float*)d_in[6];
    const float* Wo = (const float*)d_in[7];
    const float* bo = (const float*)d_in[8];
    float* out = (float*)d_out;

    __half *Qp, *Kp, *Vp, *Cp;
    cudaGetSymbolAddress((void**)&Qp, g_Qh);
    cudaGetSymbolAddress((void**)&Kp, g_Kh);
    cudaGetSymbolAddress((void**)&Vp, g_Vh);
    cudaGetSymbolAddress((void**)&Cp, g_ctxh);

    cudaFuncSetAttribute(gemm_qkv,
                         cudaFuncAttributeMaxDynamicSharedMemorySize, GEMM_SMEM);
    cudaFuncSetAttribute(gemm_out,
                         cudaFuncAttributeMaxDynamicSharedMemorySize, GEMM_SMEM);

    // fp32 -> fp16 prep: X + 4 weight tensors  (8.39M elems / 4 per thread)
    cvt_all<<<(NX + 4 * NW) / 4 / 256, 256>>>(x, Wq, Wk, Wv, Wo);

    gemm_qkv<<<dim3(M_ / 128, 3 * H_), 256, GEMM_SMEM>>>(bq, bk, bv);

    attn_h<<<dim3(S_ / 128, B_ * H_), 256, ATT_SMEM>>>(Qp, Kp, Vp, Cp);

    gemm_out<<<dim3(M_ / 128, D_ / 64), 256, GEMM_SMEM>>>(bo, out);
}